// round 14
// baseline (speedup 1.0000x reference)
#include <cuda_runtime.h>
#include <cuda_fp16.h>
#include <math.h>
#include <cstdint>

#define SEQ   4096
#define HID   2048
#define NHEADS 16
#define HD    128
#define QKVN  6144

// fp16 planes (hi only — pure fp16 with fp32 accumulate)
__device__ __half g_hid_h[SEQ * HID];
__device__ __half g_wq_h[QKVN * HID];
__device__ __half g_wo_h[HID * HID];
__device__ __half g_at_h[SEQ * HID];

// attention planes, [head][seq][128]
__device__ __half g_qh[NHEADS * SEQ * HD];
__device__ __half g_kh[NHEADS * SEQ * HD];
__device__ __half g_vh[NHEADS * SEQ * HD];

// RoPE table
__device__ float2 g_rope[SEQ * 64];

// ---------------------------------------------------------------------------
__device__ __forceinline__ uint32_t smem_u32(const void* p) {
    uint32_t a;
    asm("{ .reg .u64 t; cvta.to.shared.u64 t, %1; cvt.u32.u64 %0, t; }"
        : "=r"(a) : "l"(p));
    return a;
}

__device__ __forceinline__ void ldsm4(uint32_t* r, uint32_t addr) {
    asm volatile("ldmatrix.sync.aligned.m8n8.x4.shared.b16 {%0,%1,%2,%3}, [%4];"
                 : "=r"(r[0]), "=r"(r[1]), "=r"(r[2]), "=r"(r[3]) : "r"(addr));
}

__device__ __forceinline__ void ldsm4t(uint32_t* r, uint32_t addr) {
    asm volatile("ldmatrix.sync.aligned.m8n8.x4.trans.shared.b16 {%0,%1,%2,%3}, [%4];"
                 : "=r"(r[0]), "=r"(r[1]), "=r"(r[2]), "=r"(r[3]) : "r"(addr));
}

__device__ __forceinline__ void mma16816(float* c, const uint32_t* a, const uint32_t* b) {
    asm volatile(
        "mma.sync.aligned.m16n8k16.row.col.f32.f16.f16.f32 "
        "{%0,%1,%2,%3}, {%4,%5,%6,%7}, {%8,%9}, {%0,%1,%2,%3};"
        : "+f"(c[0]), "+f"(c[1]), "+f"(c[2]), "+f"(c[3])
        : "r"(a[0]), "r"(a[1]), "r"(a[2]), "r"(a[3]), "r"(b[0]), "r"(b[1]));
}

__device__ __forceinline__ void cpasync16(uint32_t sa, const void* ga) {
    asm volatile("cp.async.cg.shared.global [%0], [%1], 16;" :: "r"(sa), "l"(ga));
}

__device__ __forceinline__ uint32_t pack_hi(float x, float y) {
    __half2 hb = __floats2half2_rn(x, y);
    return *(uint32_t*)&hb;
}

// ---------------------------------------------------------------------------
__global__ void __launch_bounds__(256) rope_table_kernel()
{
    int idx = blockIdx.x * 256 + threadIdx.x;
    if (idx >= SEQ * 64) return;
    int pos = idx >> 6, f = idx & 63;
    float inv = 1.0f / powf(10000.0f, (float)(2 * f) / 128.0f);
    float a = (float)pos * inv;
    g_rope[idx] = make_float2(cosf(a), sinf(a));
}

// fp32 -> fp16
__global__ void __launch_bounds__(256) cvt_kernel(
    const float* __restrict__ in, __half* __restrict__ hi, int n4)
{
    int i = blockIdx.x * 256 + threadIdx.x;
    if (i >= n4) return;
    float4 v = ((const float4*)in)[i];
    ((uint2*)hi)[i] = make_uint2(pack_hi(v.x, v.y), pack_hi(v.z, v.w));
}

// ---------------------------------------------------------------------------
// fp16 HMMA GEMM NT: C = Ah * Bh^T, fp32 accumulate.
// CTA 128x128, BK=64 (halved barrier count), 2-stage cp.async, 8 warps (4x2),
// warp tile 32x64. mode 0: fp32 C. mode 1: fused table-RoPE(+q scale) epilogue.
// ---------------------------------------------------------------------------
#define GPITCH 144               // 64 halfs = 128B data + 16B pad
#define PLANE  (128 * GPITCH)    // 18432 per plane
#define STAGE  (2 * PLANE)       // 36864 per stage (Ah, Bh)

__global__ void __launch_bounds__(256, 2)
gemm_fp16(const __half* __restrict__ Ah, const __half* __restrict__ Bh,
          float* __restrict__ C, int M, int N, int K, int mode)
{
    extern __shared__ char smc[];
    uint32_t sbase = smem_u32(smc);

    const int tid  = threadIdx.x;
    const int lane = tid & 31;
    const int wid  = tid >> 5;
    const int m0 = blockIdx.y * 128;
    const int n0 = blockIdx.x * 128;
    const int wm = (wid & 3) * 32;
    const int wn = (wid >> 2) * 64;

    const __half* gA0 = Ah + (size_t)m0 * K;
    const __half* gB0 = Bh + (size_t)n0 * K;

    auto load_stage = [&](int s, int k0) {
        uint32_t sp = sbase + s * STAGE;
        #pragma unroll
        for (int i = 0; i < 4; i++) {
            int idx = tid + i * 256;      // 0..1023
            int r = idx >> 3;             // 0..127
            int c = idx & 7;              // 16B chunk within 128B row
            uint32_t so = r * GPITCH + c * 16;
            size_t go = (size_t)r * K + k0 + c * 8;
            cpasync16(sp + so,         gA0 + go);
            cpasync16(sp + PLANE + so, gB0 + go);
        }
        asm volatile("cp.async.commit_group;");
    };

    float acc[2][8][4];
    #pragma unroll
    for (int a = 0; a < 2; a++)
        #pragma unroll
        for (int b = 0; b < 8; b++)
            #pragma unroll
            for (int c = 0; c < 4; c++) acc[a][b][c] = 0.f;

    const int nk = K >> 6;
    load_stage(0, 0);

    const int grp = lane >> 3, r8 = lane & 7;
    const int arow_off = r8 + ((grp & 1) << 3);
    const int akk_off  = (grp >> 1) << 3;
    const int brow_off = r8 + ((grp >> 1) << 3);
    const int bkk_off  = (grp & 1) << 3;

    for (int kt = 0; kt < nk; kt++) {
        int cur = kt & 1;
        if (kt + 1 < nk) {
            load_stage(cur ^ 1, (kt + 1) << 6);
            asm volatile("cp.async.wait_group 1;");
        } else {
            asm volatile("cp.async.wait_group 0;");
        }
        __syncthreads();

        uint32_t stg = sbase + cur * STAGE;
        uint32_t sAh = stg, sBh = stg + PLANE;

        #pragma unroll
        for (int ks = 0; ks < 4; ks++) {
            int kb = ks * 16;
            uint32_t a_h[2][4];
            #pragma unroll
            for (int mt = 0; mt < 2; mt++) {
                uint32_t ad = (uint32_t)((wm + mt * 16 + arow_off) * GPITCH
                                         + (kb + akk_off) * 2);
                ldsm4(a_h[mt], sAh + ad);
            }
            #pragma unroll
            for (int np = 0; np < 4; np++) {
                uint32_t bh[4];
                uint32_t bd = (uint32_t)((wn + np * 16 + brow_off) * GPITCH
                                         + (kb + bkk_off) * 2);
                ldsm4(bh, sBh + bd);
                #pragma unroll
                for (int mt = 0; mt < 2; mt++) {
                    mma16816(acc[mt][np * 2],     a_h[mt], &bh[0]);
                    mma16816(acc[mt][np * 2 + 1], a_h[mt], &bh[2]);
                }
            }
        }
        __syncthreads();
    }

    if (mode == 0) {
        #pragma unroll
        for (int mt = 0; mt < 2; mt++) {
            int row0 = m0 + wm + mt * 16 + (lane >> 2);
            #pragma unroll
            for (int nt = 0; nt < 8; nt++) {
                int col = n0 + wn + nt * 8 + (lane & 3) * 2;
                *(float2*)(C + (size_t)row0 * N + col) =
                    make_float2(acc[mt][nt][0], acc[mt][nt][1]);
                *(float2*)(C + (size_t)(row0 + 8) * N + col) =
                    make_float2(acc[mt][nt][2], acc[mt][nt][3]);
            }
        }
    } else {
        // QKV epilogue: fp32 tile via smem, table RoPE + scale, fp16 planes
        const int PITW = 134;   // 128*134*4 = 68608 <= 73728
        float* sf = (float*)smc;
        #pragma unroll
        for (int mt = 0; mt < 2; mt++) {
            int r0 = wm + mt * 16 + (lane >> 2);
            #pragma unroll
            for (int nt = 0; nt < 8; nt++) {
                int c = wn + nt * 8 + (lane & 3) * 2;
                sf[r0 * PITW + c]           = acc[mt][nt][0];
                sf[r0 * PITW + c + 1]       = acc[mt][nt][1];
                sf[(r0 + 8) * PITW + c]     = acc[mt][nt][2];
                sf[(r0 + 8) * PITW + c + 1] = acc[mt][nt][3];
            }
        }
        __syncthreads();

        int sec  = n0 >> 11;            // 0=q, 1=k, 2=v
        int head = (n0 >> 7) & 15;
        __half* dst = (sec == 0) ? g_qh : (sec == 1) ? g_kh : g_vh;
        size_t base_o = (size_t)head * SEQ * HD;
        float qscale = (sec == 0) ? 0.08838834764831845f : 1.0f;

        #pragma unroll 4
        for (int it = 0; it < 16; it++) {
            int idx = tid + it * 256;
            int r = idx >> 5;
            int i = (idx & 31) * 2;
            float x0 = sf[r * PITW + i],      x1 = sf[r * PITW + i + 1];
            float y0 = sf[r * PITW + i + 64], y1 = sf[r * PITW + i + 65];
            float re0, re1, im0, im1;
            if (sec < 2) {
                float4 t = *(float4*)&g_rope[(size_t)(m0 + r) * 64 + i];
                re0 = (x0 * t.x - y0 * t.y) * qscale;
                im0 = (y0 * t.x + x0 * t.y) * qscale;
                re1 = (x1 * t.z - y1 * t.w) * qscale;
                im1 = (y1 * t.z + x1 * t.w) * qscale;
            } else {
                re0 = x0; re1 = x1; im0 = y0; im1 = y1;
            }
            size_t o = base_o + (size_t)(m0 + r) * HD + i;
            *(uint32_t*)(dst + o)      = pack_hi(re0, re1);
            *(uint32_t*)(dst + o + 64) = pack_hi(im0, im1);
        }
    }
}

// ---------------------------------------------------------------------------
// fp16 HMMA flash attention (round-12 verified form).
// ---------------------------------------------------------------------------
#define FSW(row, c16) (((row) << 8) + ((((c16) ^ ((row) & 7))) << 4))
#define KVPL 16384
#define KVST 32768

__global__ void __launch_bounds__(256) flash_hmma()
{
    extern __shared__ char fsm[];
    uint32_t sQh = smem_u32(fsm);
    uint32_t sKV = sQh + 32768;

    const int tid  = threadIdx.x;
    const int lane = tid & 31;
    const int w    = tid >> 5;
    const int head = blockIdx.y;
    const int q0   = ((int)gridDim.x - 1 - (int)blockIdx.x) * 128;

    const size_t hoff = (size_t)head * SEQ * HD;
    const __half* Qh = g_qh + hoff;
    const __half* Kh = g_kh + hoff;
    const __half* Vh = g_vh + hoff;

    #pragma unroll
    for (int i = 0; i < 8; i++) {
        int idx = tid + i * 256;
        int r = idx >> 4, c16 = idx & 15;
        cpasync16(sQh + FSW(r, c16), Qh + (size_t)(q0 + r) * HD + c16 * 8);
    }

    auto load_kv = [&](int kt) {
        int k0 = kt << 6;
        uint32_t st = sKV + (kt & 1) * KVST;
        #pragma unroll
        for (int i = 0; i < 4; i++) {
            int idx = tid + i * 256;
            int r = idx >> 4, c16 = idx & 15;
            uint32_t o = FSW(r, c16);
            size_t go = (size_t)(k0 + r) * HD + c16 * 8;
            cpasync16(st + o,        Kh + go);
            cpasync16(st + KVPL + o, Vh + go);
        }
        asm volatile("cp.async.commit_group;");
    };

    const int ntk = (q0 >> 6) + 2;
    load_kv(0);

    const int grp = lane >> 3, r8 = lane & 7;
    const int arow = r8 + ((grp & 1) << 3);
    const int ac16 = grp >> 1;
    const int brow = r8 + ((grp >> 1) << 3);
    const int bc16 = grp & 1;

    float o[16][4];
    #pragma unroll
    for (int i = 0; i < 16; i++)
        #pragma unroll
        for (int j = 0; j < 4; j++) o[i][j] = 0.f;
    float m0 = -1e30f, m1 = -1e30f, l0 = 0.f, l1 = 0.f;

    const int row0 = q0 + w * 16 + (lane >> 2);
    const int wlast = q0 + w * 16 + 15;

    for (int kt = 0; kt < ntk; kt++) {
        int k0 = kt << 6;
        int cur = kt & 1;
        if (kt + 1 < ntk) {
            load_kv(kt + 1);
            asm volatile("cp.async.wait_group 1;");
        } else {
            asm volatile("cp.async.wait_group 0;");
        }
        __syncthreads();

        if (k0 <= wlast) {
            uint32_t st = sKV + cur * KVST;
            uint32_t sKh = st, sVh = st + KVPL;

            float sc[8][4];
            #pragma unroll
            for (int i = 0; i < 8; i++)
                #pragma unroll
                for (int j = 0; j < 4; j++) sc[i][j] = 0.f;

            #pragma unroll
            for (int ks = 0; ks < 8; ks++) {
                uint32_t qh[4];
                int qr = w * 16 + arow, qc = ks * 2 + ac16;
                ldsm4(qh, sQh + FSW(qr, qc));
                #pragma unroll
                for (int g = 0; g < 4; g++) {
                    uint32_t kh[4];
                    int kr = g * 16 + brow, kc = ks * 2 + bc16;
                    ldsm4(kh, sKh + FSW(kr, kc));
                    mma16816(sc[g * 2],     qh, &kh[0]);
                    mma16816(sc[g * 2 + 1], qh, &kh[2]);
                }
            }

            if (k0 + 63 > row0) {
                #pragma unroll
                for (int nt = 0; nt < 8; nt++) {
                    int colb = k0 + nt * 8 + (lane & 3) * 2;
                    if (colb > row0)     sc[nt][0] = -1e30f;
                    if (colb + 1 > row0) sc[nt][1] = -1e30f;
                    if (colb > row0 + 8)     sc[nt][2] = -1e30f;
                    if (colb + 1 > row0 + 8) sc[nt][3] = -1e30f;
                }
            }

            float mt0 = -1e30f, mt1 = -1e30f;
            #pragma unroll
            for (int nt = 0; nt < 8; nt++) {
                mt0 = fmaxf(mt0, fmaxf(sc[nt][0], sc[nt][1]));
                mt1 = fmaxf(mt1, fmaxf(sc[nt][2], sc[nt][3]));
            }
            mt0 = fmaxf(mt0, __shfl_xor_sync(0xffffffffu, mt0, 1));
            mt0 = fmaxf(mt0, __shfl_xor_sync(0xffffffffu, mt0, 2));
            mt1 = fmaxf(mt1, __shfl_xor_sync(0xffffffffu, mt1, 1));
            mt1 = fmaxf(mt1, __shfl_xor_sync(0xffffffffu, mt1, 2));
            float mn0 = fmaxf(m0, mt0), mn1 = fmaxf(m1, mt1);
            float f0 = __expf(m0 - mn0), f1 = __expf(m1 - mn1);
            m0 = mn0; m1 = mn1;

            float s0 = 0.f, s1 = 0.f;
            #pragma unroll
            for (int nt = 0; nt < 8; nt++) {
                sc[nt][0] = __expf(sc[nt][0] - mn0); s0 += sc[nt][0];
                sc[nt][1] = __expf(sc[nt][1] - mn0); s0 += sc[nt][1];
                sc[nt][2] = __expf(sc[nt][2] - mn1); s1 += sc[nt][2];
                sc[nt][3] = __expf(sc[nt][3] - mn1); s1 += sc[nt][3];
            }
            s0 += __shfl_xor_sync(0xffffffffu, s0, 1);
            s0 += __shfl_xor_sync(0xffffffffu, s0, 2);
            s1 += __shfl_xor_sync(0xffffffffu, s1, 1);
            s1 += __shfl_xor_sync(0xffffffffu, s1, 2);
            l0 = l0 * f0 + s0;
            l1 = l1 * f1 + s1;

            #pragma unroll
            for (int i = 0; i < 16; i++) {
                o[i][0] *= f0; o[i][1] *= f0;
                o[i][2] *= f1; o[i][3] *= f1;
            }

            #pragma unroll
            for (int ks = 0; ks < 4; ks++) {
                uint32_t ph[4];
                int t0 = ks * 2, t1 = ks * 2 + 1;
                ph[0] = pack_hi(sc[t0][0], sc[t0][1]);
                ph[1] = pack_hi(sc[t0][2], sc[t0][3]);
                ph[2] = pack_hi(sc[t1][0], sc[t1][1]);
                ph[3] = pack_hi(sc[t1][2], sc[t1][3]);
                #pragma unroll
                for (int g = 0; g < 8; g++) {
                    uint32_t vh[4];
                    int vr = ks * 16 + arow, vc = g * 2 + ac16;
                    ldsm4t(vh, sVh + FSW(vr, vc));
                    mma16816(o[g * 2],     ph, &vh[0]);
                    mma16816(o[g * 2 + 1], ph, &vh[2]);
                }
            }
        }
        __syncthreads();
    }

    float il0 = 1.0f / l0, il1 = 1.0f / l1;
    #pragma unroll
    for (int dt = 0; dt < 16; dt++) {
        int col = head * HD + dt * 8 + (lane & 3) * 2;
        *(uint32_t*)(g_at_h + (size_t)row0 * HID + col) =
            pack_hi(o[dt][0] * il0, o[dt][1] * il0);
        *(uint32_t*)(g_at_h + (size_t)(row0 + 8) * HID + col) =
            pack_hi(o[dt][2] * il1, o[dt][3] * il1);
    }
}

// ---------------------------------------------------------------------------
extern "C" void kernel_launch(void* const* d_in, const int* in_sizes, int n_in,
                              void* d_out, int out_size)
{
    const float* hidden = (const float*)d_in[0];
    const float* w_qkv  = (const float*)d_in[1];
    const float* w_o    = (const float*)d_in[2];
    float* out = (float*)d_out;

    __half *hid_h, *wq_h, *wo_h, *at_h;
    cudaGetSymbolAddress((void**)&hid_h, g_hid_h);
    cudaGetSymbolAddress((void**)&wq_h, g_wq_h);
    cudaGetSymbolAddress((void**)&wo_h, g_wo_h);
    cudaGetSymbolAddress((void**)&at_h, g_at_h);

    const int gemm_smem = 2 * STAGE;   // 73728
    cudaFuncSetAttribute(gemm_fp16,
                         cudaFuncAttributeMaxDynamicSharedMemorySize, gemm_smem);

    rope_table_kernel<<<SEQ * 64 / 256, 256>>>();
    cvt_kernel<<<(SEQ * HID / 4 + 255) / 256, 256>>>(hidden, hid_h, SEQ * HID / 4);
    cvt_kernel<<<(QKVN * HID / 4 + 255) / 256, 256>>>(w_qkv, wq_h, QKVN * HID / 4);
    cvt_kernel<<<(HID * HID / 4 + 255) / 256, 256>>>(w_o, wo_h, HID * HID / 4);

    // 1) QKV projection + fused RoPE/split epilogue
    gemm_fp16<<<dim3(QKVN / 128, SEQ / 128), 256, gemm_smem>>>(
        hid_h, wq_h, nullptr, SEQ, QKVN, HID, 1);

    // 2) flash attention
    const int fl_smem = 32768 + 2 * KVST;   // 98304
    cudaFuncSetAttribute(flash_hmma,
                         cudaFuncAttributeMaxDynamicSharedMemorySize, fl_smem);
    flash_hmma<<<dim3(SEQ / 128, NHEADS), 256, fl_smem>>>();

    // 3) O projection
    gemm_fp16<<<dim3(HID / 128, SEQ / 128), 256, gemm_smem>>>(
        at_h, wo_h, out, SEQ, HID, HID, 0);
}

// round 15
// speedup vs baseline: 1.0009x; 1.0009x over previous
#include <cuda_runtime.h>
#include <cuda_fp16.h>
#include <math.h>
#include <cstdint>

#define SEQ   4096
#define HID   2048
#define NHEADS 16
#define HD    128
#define QKVN  6144

// fp16 planes (hi only — pure fp16 with fp32 accumulate)
__device__ __half g_hid_h[SEQ * HID];
__device__ __half g_wq_h[QKVN * HID];
__device__ __half g_wo_h[HID * HID];
__device__ __half g_at_h[SEQ * HID];

// attention planes, [head][seq][128]
__device__ __half g_qh[NHEADS * SEQ * HD];
__device__ __half g_kh[NHEADS * SEQ * HD];
__device__ __half g_vh[NHEADS * SEQ * HD];

// RoPE table
__device__ float2 g_rope[SEQ * 64];

// ---------------------------------------------------------------------------
__device__ __forceinline__ uint32_t smem_u32(const void* p) {
    uint32_t a;
    asm("{ .reg .u64 t; cvta.to.shared.u64 t, %1; cvt.u32.u64 %0, t; }"
        : "=r"(a) : "l"(p));
    return a;
}

__device__ __forceinline__ void ldsm4(uint32_t* r, uint32_t addr) {
    asm volatile("ldmatrix.sync.aligned.m8n8.x4.shared.b16 {%0,%1,%2,%3}, [%4];"
                 : "=r"(r[0]), "=r"(r[1]), "=r"(r[2]), "=r"(r[3]) : "r"(addr));
}

__device__ __forceinline__ void ldsm4t(uint32_t* r, uint32_t addr) {
    asm volatile("ldmatrix.sync.aligned.m8n8.x4.trans.shared.b16 {%0,%1,%2,%3}, [%4];"
                 : "=r"(r[0]), "=r"(r[1]), "=r"(r[2]), "=r"(r[3]) : "r"(addr));
}

__device__ __forceinline__ void mma16816(float* c, const uint32_t* a, const uint32_t* b) {
    asm volatile(
        "mma.sync.aligned.m16n8k16.row.col.f32.f16.f16.f32 "
        "{%0,%1,%2,%3}, {%4,%5,%6,%7}, {%8,%9}, {%0,%1,%2,%3};"
        : "+f"(c[0]), "+f"(c[1]), "+f"(c[2]), "+f"(c[3])
        : "r"(a[0]), "r"(a[1]), "r"(a[2]), "r"(a[3]), "r"(b[0]), "r"(b[1]));
}

__device__ __forceinline__ void cpasync16(uint32_t sa, const void* ga) {
    asm volatile("cp.async.cg.shared.global [%0], [%1], 16;" :: "r"(sa), "l"(ga));
}

__device__ __forceinline__ uint32_t pack_hi(float x, float y) {
    __half2 hb = __floats2half2_rn(x, y);
    return *(uint32_t*)&hb;
}

// ---------------------------------------------------------------------------
__global__ void __launch_bounds__(256) rope_table_kernel()
{
    int idx = blockIdx.x * 256 + threadIdx.x;
    if (idx >= SEQ * 64) return;
    int pos = idx >> 6, f = idx & 63;
    float inv = 1.0f / powf(10000.0f, (float)(2 * f) / 128.0f);
    float a = (float)pos * inv;
    g_rope[idx] = make_float2(cosf(a), sinf(a));
}

// fp32 -> fp16
__global__ void __launch_bounds__(256) cvt_kernel(
    const float* __restrict__ in, __half* __restrict__ hi, int n4)
{
    int i = blockIdx.x * 256 + threadIdx.x;
    if (i >= n4) return;
    float4 v = ((const float4*)in)[i];
    ((uint2*)hi)[i] = make_uint2(pack_hi(v.x, v.y), pack_hi(v.z, v.w));
}

// ---------------------------------------------------------------------------
// fp16 HMMA GEMM NT: C = Ah * Bh^T, fp32 accumulate.
// CTA 128x128, BK=64 (halved barrier count), 2-stage cp.async, 8 warps (4x2),
// warp tile 32x64. mode 0: fp32 C. mode 1: fused table-RoPE(+q scale) epilogue.
// ---------------------------------------------------------------------------
#define GPITCH 144               // 64 halfs = 128B data + 16B pad
#define PLANE  (128 * GPITCH)    // 18432 per plane
#define STAGE  (2 * PLANE)       // 36864 per stage (Ah, Bh)

__global__ void __launch_bounds__(256, 2)
gemm_fp16(const __half* __restrict__ Ah, const __half* __restrict__ Bh,
          float* __restrict__ C, int M, int N, int K, int mode)
{
    extern __shared__ char smc[];
    uint32_t sbase = smem_u32(smc);

    const int tid  = threadIdx.x;
    const int lane = tid & 31;
    const int wid  = tid >> 5;
    const int m0 = blockIdx.y * 128;
    const int n0 = blockIdx.x * 128;
    const int wm = (wid & 3) * 32;
    const int wn = (wid >> 2) * 64;

    const __half* gA0 = Ah + (size_t)m0 * K;
    const __half* gB0 = Bh + (size_t)n0 * K;

    auto load_stage = [&](int s, int k0) {
        uint32_t sp = sbase + s * STAGE;
        #pragma unroll
        for (int i = 0; i < 4; i++) {
            int idx = tid + i * 256;      // 0..1023
            int r = idx >> 3;             // 0..127
            int c = idx & 7;              // 16B chunk within 128B row
            uint32_t so = r * GPITCH + c * 16;
            size_t go = (size_t)r * K + k0 + c * 8;
            cpasync16(sp + so,         gA0 + go);
            cpasync16(sp + PLANE + so, gB0 + go);
        }
        asm volatile("cp.async.commit_group;");
    };

    float acc[2][8][4];
    #pragma unroll
    for (int a = 0; a < 2; a++)
        #pragma unroll
        for (int b = 0; b < 8; b++)
            #pragma unroll
            for (int c = 0; c < 4; c++) acc[a][b][c] = 0.f;

    const int nk = K >> 6;
    load_stage(0, 0);

    const int grp = lane >> 3, r8 = lane & 7;
    const int arow_off = r8 + ((grp & 1) << 3);
    const int akk_off  = (grp >> 1) << 3;
    const int brow_off = r8 + ((grp >> 1) << 3);
    const int bkk_off  = (grp & 1) << 3;

    for (int kt = 0; kt < nk; kt++) {
        int cur = kt & 1;
        if (kt + 1 < nk) {
            load_stage(cur ^ 1, (kt + 1) << 6);
            asm volatile("cp.async.wait_group 1;");
        } else {
            asm volatile("cp.async.wait_group 0;");
        }
        __syncthreads();

        uint32_t stg = sbase + cur * STAGE;
        uint32_t sAh = stg, sBh = stg + PLANE;

        #pragma unroll
        for (int ks = 0; ks < 4; ks++) {
            int kb = ks * 16;
            uint32_t a_h[2][4];
            #pragma unroll
            for (int mt = 0; mt < 2; mt++) {
                uint32_t ad = (uint32_t)((wm + mt * 16 + arow_off) * GPITCH
                                         + (kb + akk_off) * 2);
                ldsm4(a_h[mt], sAh + ad);
            }
            #pragma unroll
            for (int np = 0; np < 4; np++) {
                uint32_t bh[4];
                uint32_t bd = (uint32_t)((wn + np * 16 + brow_off) * GPITCH
                                         + (kb + bkk_off) * 2);
                ldsm4(bh, sBh + bd);
                #pragma unroll
                for (int mt = 0; mt < 2; mt++) {
                    mma16816(acc[mt][np * 2],     a_h[mt], &bh[0]);
                    mma16816(acc[mt][np * 2 + 1], a_h[mt], &bh[2]);
                }
            }
        }
        __syncthreads();
    }

    if (mode == 0) {
        #pragma unroll
        for (int mt = 0; mt < 2; mt++) {
            int row0 = m0 + wm + mt * 16 + (lane >> 2);
            #pragma unroll
            for (int nt = 0; nt < 8; nt++) {
                int col = n0 + wn + nt * 8 + (lane & 3) * 2;
                *(float2*)(C + (size_t)row0 * N + col) =
                    make_float2(acc[mt][nt][0], acc[mt][nt][1]);
                *(float2*)(C + (size_t)(row0 + 8) * N + col) =
                    make_float2(acc[mt][nt][2], acc[mt][nt][3]);
            }
        }
    } else {
        // QKV epilogue: fp32 tile via smem, table RoPE + scale, fp16 planes
        const int PITW = 134;   // 128*134*4 = 68608 <= 73728
        float* sf = (float*)smc;
        #pragma unroll
        for (int mt = 0; mt < 2; mt++) {
            int r0 = wm + mt * 16 + (lane >> 2);
            #pragma unroll
            for (int nt = 0; nt < 8; nt++) {
                int c = wn + nt * 8 + (lane & 3) * 2;
                sf[r0 * PITW + c]           = acc[mt][nt][0];
                sf[r0 * PITW + c + 1]       = acc[mt][nt][1];
                sf[(r0 + 8) * PITW + c]     = acc[mt][nt][2];
                sf[(r0 + 8) * PITW + c + 1] = acc[mt][nt][3];
            }
        }
        __syncthreads();

        int sec  = n0 >> 11;            // 0=q, 1=k, 2=v
        int head = (n0 >> 7) & 15;
        __half* dst = (sec == 0) ? g_qh : (sec == 1) ? g_kh : g_vh;
        size_t base_o = (size_t)head * SEQ * HD;
        float qscale = (sec == 0) ? 0.08838834764831845f : 1.0f;

        #pragma unroll 4
        for (int it = 0; it < 16; it++) {
            int idx = tid + it * 256;
            int r = idx >> 5;
            int i = (idx & 31) * 2;
            float x0 = sf[r * PITW + i],      x1 = sf[r * PITW + i + 1];
            float y0 = sf[r * PITW + i + 64], y1 = sf[r * PITW + i + 65];
            float re0, re1, im0, im1;
            if (sec < 2) {
                float4 t = *(float4*)&g_rope[(size_t)(m0 + r) * 64 + i];
                re0 = (x0 * t.x - y0 * t.y) * qscale;
                im0 = (y0 * t.x + x0 * t.y) * qscale;
                re1 = (x1 * t.z - y1 * t.w) * qscale;
                im1 = (y1 * t.z + x1 * t.w) * qscale;
            } else {
                re0 = x0; re1 = x1; im0 = y0; im1 = y1;
            }
            size_t o = base_o + (size_t)(m0 + r) * HD + i;
            *(uint32_t*)(dst + o)      = pack_hi(re0, re1);
            *(uint32_t*)(dst + o + 64) = pack_hi(im0, im1);
        }
    }
}

// ---------------------------------------------------------------------------
// fp16 HMMA flash attention (round-12 verified form).
// ---------------------------------------------------------------------------
#define FSW(row, c16) (((row) << 8) + ((((c16) ^ ((row) & 7))) << 4))
#define KVPL 16384
#define KVST 32768

__global__ void __launch_bounds__(256) flash_hmma()
{
    extern __shared__ char fsm[];
    uint32_t sQh = smem_u32(fsm);
    uint32_t sKV = sQh + 32768;

    const int tid  = threadIdx.x;
    const int lane = tid & 31;
    const int w    = tid >> 5;
    const int head = blockIdx.y;
    const int q0   = ((int)gridDim.x - 1 - (int)blockIdx.x) * 128;

    const size_t hoff = (size_t)head * SEQ * HD;
    const __half* Qh = g_qh + hoff;
    const __half* Kh = g_kh + hoff;
    const __half* Vh = g_vh + hoff;

    #pragma unroll
    for (int i = 0; i < 8; i++) {
        int idx = tid + i * 256;
        int r = idx >> 4, c16 = idx & 15;
        cpasync16(sQh + FSW(r, c16), Qh + (size_t)(q0 + r) * HD + c16 * 8);
    }

    auto load_kv = [&](int kt) {
        int k0 = kt << 6;
        uint32_t st = sKV + (kt & 1) * KVST;
        #pragma unroll
        for (int i = 0; i < 4; i++) {
            int idx = tid + i * 256;
            int r = idx >> 4, c16 = idx & 15;
            uint32_t o = FSW(r, c16);
            size_t go = (size_t)(k0 + r) * HD + c16 * 8;
            cpasync16(st + o,        Kh + go);
            cpasync16(st + KVPL + o, Vh + go);
        }
        asm volatile("cp.async.commit_group;");
    };

    const int ntk = (q0 >> 6) + 2;
    load_kv(0);

    const int grp = lane >> 3, r8 = lane & 7;
    const int arow = r8 + ((grp & 1) << 3);
    const int ac16 = grp >> 1;
    const int brow = r8 + ((grp >> 1) << 3);
    const int bc16 = grp & 1;

    float o[16][4];
    #pragma unroll
    for (int i = 0; i < 16; i++)
        #pragma unroll
        for (int j = 0; j < 4; j++) o[i][j] = 0.f;
    float m0 = -1e30f, m1 = -1e30f, l0 = 0.f, l1 = 0.f;

    const int row0 = q0 + w * 16 + (lane >> 2);
    const int wlast = q0 + w * 16 + 15;

    for (int kt = 0; kt < ntk; kt++) {
        int k0 = kt << 6;
        int cur = kt & 1;
        if (kt + 1 < ntk) {
            load_kv(kt + 1);
            asm volatile("cp.async.wait_group 1;");
        } else {
            asm volatile("cp.async.wait_group 0;");
        }
        __syncthreads();

        if (k0 <= wlast) {
            uint32_t st = sKV + cur * KVST;
            uint32_t sKh = st, sVh = st + KVPL;

            float sc[8][4];
            #pragma unroll
            for (int i = 0; i < 8; i++)
                #pragma unroll
                for (int j = 0; j < 4; j++) sc[i][j] = 0.f;

            #pragma unroll
            for (int ks = 0; ks < 8; ks++) {
                uint32_t qh[4];
                int qr = w * 16 + arow, qc = ks * 2 + ac16;
                ldsm4(qh, sQh + FSW(qr, qc));
                #pragma unroll
                for (int g = 0; g < 4; g++) {
                    uint32_t kh[4];
                    int kr = g * 16 + brow, kc = ks * 2 + bc16;
                    ldsm4(kh, sKh + FSW(kr, kc));
                    mma16816(sc[g * 2],     qh, &kh[0]);
                    mma16816(sc[g * 2 + 1], qh, &kh[2]);
                }
            }

            if (k0 + 63 > row0) {
                #pragma unroll
                for (int nt = 0; nt < 8; nt++) {
                    int colb = k0 + nt * 8 + (lane & 3) * 2;
                    if (colb > row0)     sc[nt][0] = -1e30f;
                    if (colb + 1 > row0) sc[nt][1] = -1e30f;
                    if (colb > row0 + 8)     sc[nt][2] = -1e30f;
                    if (colb + 1 > row0 + 8) sc[nt][3] = -1e30f;
                }
            }

            float mt0 = -1e30f, mt1 = -1e30f;
            #pragma unroll
            for (int nt = 0; nt < 8; nt++) {
                mt0 = fmaxf(mt0, fmaxf(sc[nt][0], sc[nt][1]));
                mt1 = fmaxf(mt1, fmaxf(sc[nt][2], sc[nt][3]));
            }
            mt0 = fmaxf(mt0, __shfl_xor_sync(0xffffffffu, mt0, 1));
            mt0 = fmaxf(mt0, __shfl_xor_sync(0xffffffffu, mt0, 2));
            mt1 = fmaxf(mt1, __shfl_xor_sync(0xffffffffu, mt1, 1));
            mt1 = fmaxf(mt1, __shfl_xor_sync(0xffffffffu, mt1, 2));
            float mn0 = fmaxf(m0, mt0), mn1 = fmaxf(m1, mt1);
            float f0 = __expf(m0 - mn0), f1 = __expf(m1 - mn1);
            m0 = mn0; m1 = mn1;

            float s0 = 0.f, s1 = 0.f;
            #pragma unroll
            for (int nt = 0; nt < 8; nt++) {
                sc[nt][0] = __expf(sc[nt][0] - mn0); s0 += sc[nt][0];
                sc[nt][1] = __expf(sc[nt][1] - mn0); s0 += sc[nt][1];
                sc[nt][2] = __expf(sc[nt][2] - mn1); s1 += sc[nt][2];
                sc[nt][3] = __expf(sc[nt][3] - mn1); s1 += sc[nt][3];
            }
            s0 += __shfl_xor_sync(0xffffffffu, s0, 1);
            s0 += __shfl_xor_sync(0xffffffffu, s0, 2);
            s1 += __shfl_xor_sync(0xffffffffu, s1, 1);
            s1 += __shfl_xor_sync(0xffffffffu, s1, 2);
            l0 = l0 * f0 + s0;
            l1 = l1 * f1 + s1;

            #pragma unroll
            for (int i = 0; i < 16; i++) {
                o[i][0] *= f0; o[i][1] *= f0;
                o[i][2] *= f1; o[i][3] *= f1;
            }

            #pragma unroll
            for (int ks = 0; ks < 4; ks++) {
                uint32_t ph[4];
                int t0 = ks * 2, t1 = ks * 2 + 1;
                ph[0] = pack_hi(sc[t0][0], sc[t0][1]);
                ph[1] = pack_hi(sc[t0][2], sc[t0][3]);
                ph[2] = pack_hi(sc[t1][0], sc[t1][1]);
                ph[3] = pack_hi(sc[t1][2], sc[t1][3]);
                #pragma unroll
                for (int g = 0; g < 8; g++) {
                    uint32_t vh[4];
                    int vr = ks * 16 + arow, vc = g * 2 + ac16;
                    ldsm4t(vh, sVh + FSW(vr, vc));
                    mma16816(o[g * 2],     ph, &vh[0]);
                    mma16816(o[g * 2 + 1], ph, &vh[2]);
                }
            }
        }
        __syncthreads();
    }

    float il0 = 1.0f / l0, il1 = 1.0f / l1;
    #pragma unroll
    for (int dt = 0; dt < 16; dt++) {
        int col = head * HD + dt * 8 + (lane & 3) * 2;
        *(uint32_t*)(g_at_h + (size_t)row0 * HID + col) =
            pack_hi(o[dt][0] * il0, o[dt][1] * il0);
        *(uint32_t*)(g_at_h + (size_t)(row0 + 8) * HID + col) =
            pack_hi(o[dt][2] * il1, o[dt][3] * il1);
    }
}

// ---------------------------------------------------------------------------
extern "C" void kernel_launch(void* const* d_in, const int* in_sizes, int n_in,
                              void* d_out, int out_size)
{
    const float* hidden = (const float*)d_in[0];
    const float* w_qkv  = (const float*)d_in[1];
    const float* w_o    = (const float*)d_in[2];
    float* out = (float*)d_out;

    __half *hid_h, *wq_h, *wo_h, *at_h;
    cudaGetSymbolAddress((void**)&hid_h, g_hid_h);
    cudaGetSymbolAddress((void**)&wq_h, g_wq_h);
    cudaGetSymbolAddress((void**)&wo_h, g_wo_h);
    cudaGetSymbolAddress((void**)&at_h, g_at_h);

    const int gemm_smem = 2 * STAGE;   // 73728
    cudaFuncSetAttribute(gemm_fp16,
                         cudaFuncAttributeMaxDynamicSharedMemorySize, gemm_smem);

    rope_table_kernel<<<SEQ * 64 / 256, 256>>>();
    cvt_kernel<<<(SEQ * HID / 4 + 255) / 256, 256>>>(hidden, hid_h, SEQ * HID / 4);
    cvt_kernel<<<(QKVN * HID / 4 + 255) / 256, 256>>>(w_qkv, wq_h, QKVN * HID / 4);
    cvt_kernel<<<(HID * HID / 4 + 255) / 256, 256>>>(w_o, wo_h, HID * HID / 4);

    // 1) QKV projection + fused RoPE/split epilogue
    gemm_fp16<<<dim3(QKVN / 128, SEQ / 128), 256, gemm_smem>>>(
        hid_h, wq_h, nullptr, SEQ, QKVN, HID, 1);

    // 2) flash attention
    const int fl_smem = 32768 + 2 * KVST;   // 98304
    cudaFuncSetAttribute(flash_hmma,
                         cudaFuncAttributeMaxDynamicSharedMemorySize, fl_smem);
    flash_hmma<<<dim3(SEQ / 128, NHEADS), 256, fl_smem>>>();

    // 3) O projection
    gemm_fp16<<<dim3(HID / 128, SEQ / 128), 256, gemm_smem>>>(
        at_h, wo_h, out, SEQ, HID, HID, 0);
}

// round 16
// speedup vs baseline: 1.0009x; 1.0000x over previous
#include <cuda_runtime.h>
#include <cuda_fp16.h>
#include <math.h>
#include <cstdint>

#define SEQ   4096
#define HID   2048
#define NHEADS 16
#define HD    128
#define QKVN  6144

// fp16 planes (hi only — pure fp16 with fp32 accumulate)
__device__ __half g_hid_h[SEQ * HID];
__device__ __half g_wq_h[QKVN * HID];
__device__ __half g_wo_h[HID * HID];
__device__ __half g_at_h[SEQ * HID];

// attention planes, [head][seq][128]
__device__ __half g_qh[NHEADS * SEQ * HD];
__device__ __half g_kh[NHEADS * SEQ * HD];
__device__ __half g_vh[NHEADS * SEQ * HD];

// RoPE table
__device__ float2 g_rope[SEQ * 64];

// ---------------------------------------------------------------------------
__device__ __forceinline__ uint32_t smem_u32(const void* p) {
    uint32_t a;
    asm("{ .reg .u64 t; cvta.to.shared.u64 t, %1; cvt.u32.u64 %0, t; }"
        : "=r"(a) : "l"(p));
    return a;
}

__device__ __forceinline__ void ldsm4(uint32_t* r, uint32_t addr) {
    asm volatile("ldmatrix.sync.aligned.m8n8.x4.shared.b16 {%0,%1,%2,%3}, [%4];"
                 : "=r"(r[0]), "=r"(r[1]), "=r"(r[2]), "=r"(r[3]) : "r"(addr));
}

__device__ __forceinline__ void ldsm4t(uint32_t* r, uint32_t addr) {
    asm volatile("ldmatrix.sync.aligned.m8n8.x4.trans.shared.b16 {%0,%1,%2,%3}, [%4];"
                 : "=r"(r[0]), "=r"(r[1]), "=r"(r[2]), "=r"(r[3]) : "r"(addr));
}

__device__ __forceinline__ void mma16816(float* c, const uint32_t* a, const uint32_t* b) {
    asm volatile(
        "mma.sync.aligned.m16n8k16.row.col.f32.f16.f16.f32 "
        "{%0,%1,%2,%3}, {%4,%5,%6,%7}, {%8,%9}, {%0,%1,%2,%3};"
        : "+f"(c[0]), "+f"(c[1]), "+f"(c[2]), "+f"(c[3])
        : "r"(a[0]), "r"(a[1]), "r"(a[2]), "r"(a[3]), "r"(b[0]), "r"(b[1]));
}

__device__ __forceinline__ void cpasync16(uint32_t sa, const void* ga) {
    asm volatile("cp.async.cg.shared.global [%0], [%1], 16;" :: "r"(sa), "l"(ga));
}

__device__ __forceinline__ uint32_t pack_hi(float x, float y) {
    __half2 hb = __floats2half2_rn(x, y);
    return *(uint32_t*)&hb;
}

// ---------------------------------------------------------------------------
__global__ void __launch_bounds__(256) rope_table_kernel()
{
    int idx = blockIdx.x * 256 + threadIdx.x;
    if (idx >= SEQ * 64) return;
    int pos = idx >> 6, f = idx & 63;
    float inv = 1.0f / powf(10000.0f, (float)(2 * f) / 128.0f);
    float a = (float)pos * inv;
    g_rope[idx] = make_float2(cosf(a), sinf(a));
}

// fp32 -> fp16
__global__ void __launch_bounds__(256) cvt_kernel(
    const float* __restrict__ in, __half* __restrict__ hi, int n4)
{
    int i = blockIdx.x * 256 + threadIdx.x;
    if (i >= n4) return;
    float4 v = ((const float4*)in)[i];
    ((uint2*)hi)[i] = make_uint2(pack_hi(v.x, v.y), pack_hi(v.z, v.w));
}

// ---------------------------------------------------------------------------
// fp16 HMMA GEMM NT: C = Ah * Bh^T, fp32 accumulate.
// CTA 128x128, BK=64 (halved barrier count), 2-stage cp.async, 8 warps (4x2),
// warp tile 32x64. mode 0: fp32 C. mode 1: fused table-RoPE(+q scale) epilogue.
// ---------------------------------------------------------------------------
#define GPITCH 144               // 64 halfs = 128B data + 16B pad
#define PLANE  (128 * GPITCH)    // 18432 per plane
#define STAGE  (2 * PLANE)       // 36864 per stage (Ah, Bh)

__global__ void __launch_bounds__(256, 2)
gemm_fp16(const __half* __restrict__ Ah, const __half* __restrict__ Bh,
          float* __restrict__ C, int M, int N, int K, int mode)
{
    extern __shared__ char smc[];
    uint32_t sbase = smem_u32(smc);

    const int tid  = threadIdx.x;
    const int lane = tid & 31;
    const int wid  = tid >> 5;
    const int m0 = blockIdx.y * 128;
    const int n0 = blockIdx.x * 128;
    const int wm = (wid & 3) * 32;
    const int wn = (wid >> 2) * 64;

    const __half* gA0 = Ah + (size_t)m0 * K;
    const __half* gB0 = Bh + (size_t)n0 * K;

    auto load_stage = [&](int s, int k0) {
        uint32_t sp = sbase + s * STAGE;
        #pragma unroll
        for (int i = 0; i < 4; i++) {
            int idx = tid + i * 256;      // 0..1023
            int r = idx >> 3;             // 0..127
            int c = idx & 7;              // 16B chunk within 128B row
            uint32_t so = r * GPITCH + c * 16;
            size_t go = (size_t)r * K + k0 + c * 8;
            cpasync16(sp + so,         gA0 + go);
            cpasync16(sp + PLANE + so, gB0 + go);
        }
        asm volatile("cp.async.commit_group;");
    };

    float acc[2][8][4];
    #pragma unroll
    for (int a = 0; a < 2; a++)
        #pragma unroll
        for (int b = 0; b < 8; b++)
            #pragma unroll
            for (int c = 0; c < 4; c++) acc[a][b][c] = 0.f;

    const int nk = K >> 6;
    load_stage(0, 0);

    const int grp = lane >> 3, r8 = lane & 7;
    const int arow_off = r8 + ((grp & 1) << 3);
    const int akk_off  = (grp >> 1) << 3;
    const int brow_off = r8 + ((grp >> 1) << 3);
    const int bkk_off  = (grp & 1) << 3;

    for (int kt = 0; kt < nk; kt++) {
        int cur = kt & 1;
        if (kt + 1 < nk) {
            load_stage(cur ^ 1, (kt + 1) << 6);
            asm volatile("cp.async.wait_group 1;");
        } else {
            asm volatile("cp.async.wait_group 0;");
        }
        __syncthreads();

        uint32_t stg = sbase + cur * STAGE;
        uint32_t sAh = stg, sBh = stg + PLANE;

        #pragma unroll
        for (int ks = 0; ks < 4; ks++) {
            int kb = ks * 16;
            uint32_t a_h[2][4];
            #pragma unroll
            for (int mt = 0; mt < 2; mt++) {
                uint32_t ad = (uint32_t)((wm + mt * 16 + arow_off) * GPITCH
                                         + (kb + akk_off) * 2);
                ldsm4(a_h[mt], sAh + ad);
            }
            #pragma unroll
            for (int np = 0; np < 4; np++) {
                uint32_t bh[4];
                uint32_t bd = (uint32_t)((wn + np * 16 + brow_off) * GPITCH
                                         + (kb + bkk_off) * 2);
                ldsm4(bh, sBh + bd);
                #pragma unroll
                for (int mt = 0; mt < 2; mt++) {
                    mma16816(acc[mt][np * 2],     a_h[mt], &bh[0]);
                    mma16816(acc[mt][np * 2 + 1], a_h[mt], &bh[2]);
                }
            }
        }
        __syncthreads();
    }

    if (mode == 0) {
        #pragma unroll
        for (int mt = 0; mt < 2; mt++) {
            int row0 = m0 + wm + mt * 16 + (lane >> 2);
            #pragma unroll
            for (int nt = 0; nt < 8; nt++) {
                int col = n0 + wn + nt * 8 + (lane & 3) * 2;
                *(float2*)(C + (size_t)row0 * N + col) =
                    make_float2(acc[mt][nt][0], acc[mt][nt][1]);
                *(float2*)(C + (size_t)(row0 + 8) * N + col) =
                    make_float2(acc[mt][nt][2], acc[mt][nt][3]);
            }
        }
    } else {
        // QKV epilogue: fp32 tile via smem, table RoPE + scale, fp16 planes
        const int PITW = 134;   // 128*134*4 = 68608 <= 73728
        float* sf = (float*)smc;
        #pragma unroll
        for (int mt = 0; mt < 2; mt++) {
            int r0 = wm + mt * 16 + (lane >> 2);
            #pragma unroll
            for (int nt = 0; nt < 8; nt++) {
                int c = wn + nt * 8 + (lane & 3) * 2;
                sf[r0 * PITW + c]           = acc[mt][nt][0];
                sf[r0 * PITW + c + 1]       = acc[mt][nt][1];
                sf[(r0 + 8) * PITW + c]     = acc[mt][nt][2];
                sf[(r0 + 8) * PITW + c + 1] = acc[mt][nt][3];
            }
        }
        __syncthreads();

        int sec  = n0 >> 11;            // 0=q, 1=k, 2=v
        int head = (n0 >> 7) & 15;
        __half* dst = (sec == 0) ? g_qh : (sec == 1) ? g_kh : g_vh;
        size_t base_o = (size_t)head * SEQ * HD;
        float qscale = (sec == 0) ? 0.08838834764831845f : 1.0f;

        #pragma unroll 4
        for (int it = 0; it < 16; it++) {
            int idx = tid + it * 256;
            int r = idx >> 5;
            int i = (idx & 31) * 2;
            float x0 = sf[r * PITW + i],      x1 = sf[r * PITW + i + 1];
            float y0 = sf[r * PITW + i + 64], y1 = sf[r * PITW + i + 65];
            float re0, re1, im0, im1;
            if (sec < 2) {
                float4 t = *(float4*)&g_rope[(size_t)(m0 + r) * 64 + i];
                re0 = (x0 * t.x - y0 * t.y) * qscale;
                im0 = (y0 * t.x + x0 * t.y) * qscale;
                re1 = (x1 * t.z - y1 * t.w) * qscale;
                im1 = (y1 * t.z + x1 * t.w) * qscale;
            } else {
                re0 = x0; re1 = x1; im0 = y0; im1 = y1;
            }
            size_t o = base_o + (size_t)(m0 + r) * HD + i;
            *(uint32_t*)(dst + o)      = pack_hi(re0, re1);
            *(uint32_t*)(dst + o + 64) = pack_hi(im0, im1);
        }
    }
}

// ---------------------------------------------------------------------------
// fp16 HMMA flash attention (round-12 verified form).
// ---------------------------------------------------------------------------
#define FSW(row, c16) (((row) << 8) + ((((c16) ^ ((row) & 7))) << 4))
#define KVPL 16384
#define KVST 32768

__global__ void __launch_bounds__(256) flash_hmma()
{
    extern __shared__ char fsm[];
    uint32_t sQh = smem_u32(fsm);
    uint32_t sKV = sQh + 32768;

    const int tid  = threadIdx.x;
    const int lane = tid & 31;
    const int w    = tid >> 5;
    const int head = blockIdx.y;
    const int q0   = ((int)gridDim.x - 1 - (int)blockIdx.x) * 128;

    const size_t hoff = (size_t)head * SEQ * HD;
    const __half* Qh = g_qh + hoff;
    const __half* Kh = g_kh + hoff;
    const __half* Vh = g_vh + hoff;

    #pragma unroll
    for (int i = 0; i < 8; i++) {
        int idx = tid + i * 256;
        int r = idx >> 4, c16 = idx & 15;
        cpasync16(sQh + FSW(r, c16), Qh + (size_t)(q0 + r) * HD + c16 * 8);
    }

    auto load_kv = [&](int kt) {
        int k0 = kt << 6;
        uint32_t st = sKV + (kt & 1) * KVST;
        #pragma unroll
        for (int i = 0; i < 4; i++) {
            int idx = tid + i * 256;
            int r = idx >> 4, c16 = idx & 15;
            uint32_t o = FSW(r, c16);
            size_t go = (size_t)(k0 + r) * HD + c16 * 8;
            cpasync16(st + o,        Kh + go);
            cpasync16(st + KVPL + o, Vh + go);
        }
        asm volatile("cp.async.commit_group;");
    };

    const int ntk = (q0 >> 6) + 2;
    load_kv(0);

    const int grp = lane >> 3, r8 = lane & 7;
    const int arow = r8 + ((grp & 1) << 3);
    const int ac16 = grp >> 1;
    const int brow = r8 + ((grp >> 1) << 3);
    const int bc16 = grp & 1;

    float o[16][4];
    #pragma unroll
    for (int i = 0; i < 16; i++)
        #pragma unroll
        for (int j = 0; j < 4; j++) o[i][j] = 0.f;
    float m0 = -1e30f, m1 = -1e30f, l0 = 0.f, l1 = 0.f;

    const int row0 = q0 + w * 16 + (lane >> 2);
    const int wlast = q0 + w * 16 + 15;

    for (int kt = 0; kt < ntk; kt++) {
        int k0 = kt << 6;
        int cur = kt & 1;
        if (kt + 1 < ntk) {
            load_kv(kt + 1);
            asm volatile("cp.async.wait_group 1;");
        } else {
            asm volatile("cp.async.wait_group 0;");
        }
        __syncthreads();

        if (k0 <= wlast) {
            uint32_t st = sKV + cur * KVST;
            uint32_t sKh = st, sVh = st + KVPL;

            float sc[8][4];
            #pragma unroll
            for (int i = 0; i < 8; i++)
                #pragma unroll
                for (int j = 0; j < 4; j++) sc[i][j] = 0.f;

            #pragma unroll
            for (int ks = 0; ks < 8; ks++) {
                uint32_t qh[4];
                int qr = w * 16 + arow, qc = ks * 2 + ac16;
                ldsm4(qh, sQh + FSW(qr, qc));
                #pragma unroll
                for (int g = 0; g < 4; g++) {
                    uint32_t kh[4];
                    int kr = g * 16 + brow, kc = ks * 2 + bc16;
                    ldsm4(kh, sKh + FSW(kr, kc));
                    mma16816(sc[g * 2],     qh, &kh[0]);
                    mma16816(sc[g * 2 + 1], qh, &kh[2]);
                }
            }

            if (k0 + 63 > row0) {
                #pragma unroll
                for (int nt = 0; nt < 8; nt++) {
                    int colb = k0 + nt * 8 + (lane & 3) * 2;
                    if (colb > row0)     sc[nt][0] = -1e30f;
                    if (colb + 1 > row0) sc[nt][1] = -1e30f;
                    if (colb > row0 + 8)     sc[nt][2] = -1e30f;
                    if (colb + 1 > row0 + 8) sc[nt][3] = -1e30f;
                }
            }

            float mt0 = -1e30f, mt1 = -1e30f;
            #pragma unroll
            for (int nt = 0; nt < 8; nt++) {
                mt0 = fmaxf(mt0, fmaxf(sc[nt][0], sc[nt][1]));
                mt1 = fmaxf(mt1, fmaxf(sc[nt][2], sc[nt][3]));
            }
            mt0 = fmaxf(mt0, __shfl_xor_sync(0xffffffffu, mt0, 1));
            mt0 = fmaxf(mt0, __shfl_xor_sync(0xffffffffu, mt0, 2));
            mt1 = fmaxf(mt1, __shfl_xor_sync(0xffffffffu, mt1, 1));
            mt1 = fmaxf(mt1, __shfl_xor_sync(0xffffffffu, mt1, 2));
            float mn0 = fmaxf(m0, mt0), mn1 = fmaxf(m1, mt1);
            float f0 = __expf(m0 - mn0), f1 = __expf(m1 - mn1);
            m0 = mn0; m1 = mn1;

            float s0 = 0.f, s1 = 0.f;
            #pragma unroll
            for (int nt = 0; nt < 8; nt++) {
                sc[nt][0] = __expf(sc[nt][0] - mn0); s0 += sc[nt][0];
                sc[nt][1] = __expf(sc[nt][1] - mn0); s0 += sc[nt][1];
                sc[nt][2] = __expf(sc[nt][2] - mn1); s1 += sc[nt][2];
                sc[nt][3] = __expf(sc[nt][3] - mn1); s1 += sc[nt][3];
            }
            s0 += __shfl_xor_sync(0xffffffffu, s0, 1);
            s0 += __shfl_xor_sync(0xffffffffu, s0, 2);
            s1 += __shfl_xor_sync(0xffffffffu, s1, 1);
            s1 += __shfl_xor_sync(0xffffffffu, s1, 2);
            l0 = l0 * f0 + s0;
            l1 = l1 * f1 + s1;

            #pragma unroll
            for (int i = 0; i < 16; i++) {
                o[i][0] *= f0; o[i][1] *= f0;
                o[i][2] *= f1; o[i][3] *= f1;
            }

            #pragma unroll
            for (int ks = 0; ks < 4; ks++) {
                uint32_t ph[4];
                int t0 = ks * 2, t1 = ks * 2 + 1;
                ph[0] = pack_hi(sc[t0][0], sc[t0][1]);
                ph[1] = pack_hi(sc[t0][2], sc[t0][3]);
                ph[2] = pack_hi(sc[t1][0], sc[t1][1]);
                ph[3] = pack_hi(sc[t1][2], sc[t1][3]);
                #pragma unroll
                for (int g = 0; g < 8; g++) {
                    uint32_t vh[4];
                    int vr = ks * 16 + arow, vc = g * 2 + ac16;
                    ldsm4t(vh, sVh + FSW(vr, vc));
                    mma16816(o[g * 2],     ph, &vh[0]);
                    mma16816(o[g * 2 + 1], ph, &vh[2]);
                }
            }
        }
        __syncthreads();
    }

    float il0 = 1.0f / l0, il1 = 1.0f / l1;
    #pragma unroll
    for (int dt = 0; dt < 16; dt++) {
        int col = head * HD + dt * 8 + (lane & 3) * 2;
        *(uint32_t*)(g_at_h + (size_t)row0 * HID + col) =
            pack_hi(o[dt][0] * il0, o[dt][1] * il0);
        *(uint32_t*)(g_at_h + (size_t)(row0 + 8) * HID + col) =
            pack_hi(o[dt][2] * il1, o[dt][3] * il1);
    }
}

// ---------------------------------------------------------------------------
extern "C" void kernel_launch(void* const* d_in, const int* in_sizes, int n_in,
                              void* d_out, int out_size)
{
    const float* hidden = (const float*)d_in[0];
    const float* w_qkv  = (const float*)d_in[1];
    const float* w_o    = (const float*)d_in[2];
    float* out = (float*)d_out;

    __half *hid_h, *wq_h, *wo_h, *at_h;
    cudaGetSymbolAddress((void**)&hid_h, g_hid_h);
    cudaGetSymbolAddress((void**)&wq_h, g_wq_h);
    cudaGetSymbolAddress((void**)&wo_h, g_wo_h);
    cudaGetSymbolAddress((void**)&at_h, g_at_h);

    const int gemm_smem = 2 * STAGE;   // 73728
    cudaFuncSetAttribute(gemm_fp16,
                         cudaFuncAttributeMaxDynamicSharedMemorySize, gemm_smem);

    rope_table_kernel<<<SEQ * 64 / 256, 256>>>();
    cvt_kernel<<<(SEQ * HID / 4 + 255) / 256, 256>>>(hidden, hid_h, SEQ * HID / 4);
    cvt_kernel<<<(QKVN * HID / 4 + 255) / 256, 256>>>(w_qkv, wq_h, QKVN * HID / 4);
    cvt_kernel<<<(HID * HID / 4 + 255) / 256, 256>>>(w_o, wo_h, HID * HID / 4);

    // 1) QKV projection + fused RoPE/split epilogue
    gemm_fp16<<<dim3(QKVN / 128, SEQ / 128), 256, gemm_smem>>>(
        hid_h, wq_h, nullptr, SEQ, QKVN, HID, 1);

    // 2) flash attention
    const int fl_smem = 32768 + 2 * KVST;   // 98304
    cudaFuncSetAttribute(flash_hmma,
                         cudaFuncAttributeMaxDynamicSharedMemorySize, fl_smem);
    flash_hmma<<<dim3(SEQ / 128, NHEADS), 256, fl_smem>>>();

    // 3) O projection
    gemm_fp16<<<dim3(HID / 128, SEQ / 128), 256, gemm_smem>>>(
        at_h, wo_h, out, SEQ, HID, HID, 0);
}

// round 17
// speedup vs baseline: 1.0026x; 1.0017x over previous
#include <cuda_runtime.h>
#include <cuda_fp16.h>
#include <math.h>
#include <cstdint>

#define SEQ   4096
#define HID   2048
#define NHEADS 16
#define HD    128
#define QKVN  6144

// fp16 planes (hi only — pure fp16 with fp32 accumulate)
__device__ __half g_hid_h[SEQ * HID];
__device__ __half g_wq_h[QKVN * HID];
__device__ __half g_wo_h[HID * HID];
__device__ __half g_at_h[SEQ * HID];

// attention planes, [head][seq][128]
__device__ __half g_qh[NHEADS * SEQ * HD];
__device__ __half g_kh[NHEADS * SEQ * HD];
__device__ __half g_vh[NHEADS * SEQ * HD];

// RoPE table
__device__ float2 g_rope[SEQ * 64];

// ---------------------------------------------------------------------------
__device__ __forceinline__ uint32_t smem_u32(const void* p) {
    uint32_t a;
    asm("{ .reg .u64 t; cvta.to.shared.u64 t, %1; cvt.u32.u64 %0, t; }"
        : "=r"(a) : "l"(p));
    return a;
}

__device__ __forceinline__ void ldsm4(uint32_t* r, uint32_t addr) {
    asm volatile("ldmatrix.sync.aligned.m8n8.x4.shared.b16 {%0,%1,%2,%3}, [%4];"
                 : "=r"(r[0]), "=r"(r[1]), "=r"(r[2]), "=r"(r[3]) : "r"(addr));
}

__device__ __forceinline__ void ldsm4t(uint32_t* r, uint32_t addr) {
    asm volatile("ldmatrix.sync.aligned.m8n8.x4.trans.shared.b16 {%0,%1,%2,%3}, [%4];"
                 : "=r"(r[0]), "=r"(r[1]), "=r"(r[2]), "=r"(r[3]) : "r"(addr));
}

__device__ __forceinline__ void mma16816(float* c, const uint32_t* a, const uint32_t* b) {
    asm volatile(
        "mma.sync.aligned.m16n8k16.row.col.f32.f16.f16.f32 "
        "{%0,%1,%2,%3}, {%4,%5,%6,%7}, {%8,%9}, {%0,%1,%2,%3};"
        : "+f"(c[0]), "+f"(c[1]), "+f"(c[2]), "+f"(c[3])
        : "r"(a[0]), "r"(a[1]), "r"(a[2]), "r"(a[3]), "r"(b[0]), "r"(b[1]));
}

__device__ __forceinline__ void cpasync16(uint32_t sa, const void* ga) {
    asm volatile("cp.async.cg.shared.global [%0], [%1], 16;" :: "r"(sa), "l"(ga));
}

__device__ __forceinline__ uint32_t pack_hi(float x, float y) {
    __half2 hb = __floats2half2_rn(x, y);
    return *(uint32_t*)&hb;
}

// ---------------------------------------------------------------------------
__global__ void __launch_bounds__(256) rope_table_kernel()
{
    int idx = blockIdx.x * 256 + threadIdx.x;
    if (idx >= SEQ * 64) return;
    int pos = idx >> 6, f = idx & 63;
    float inv = 1.0f / powf(10000.0f, (float)(2 * f) / 128.0f);
    float a = (float)pos * inv;
    g_rope[idx] = make_float2(cosf(a), sinf(a));
}

// fp32 -> fp16
__global__ void __launch_bounds__(256) cvt_kernel(
    const float* __restrict__ in, __half* __restrict__ hi, int n4)
{
    int i = blockIdx.x * 256 + threadIdx.x;
    if (i >= n4) return;
    float4 v = ((const float4*)in)[i];
    ((uint2*)hi)[i] = make_uint2(pack_hi(v.x, v.y), pack_hi(v.z, v.w));
}

// ---------------------------------------------------------------------------
// fp16 HMMA GEMM NT: C = Ah * Bh^T, fp32 accumulate.
// CTA 128x128, BK=64 (halved barrier count), 2-stage cp.async, 8 warps (4x2),
// warp tile 32x64. mode 0: fp32 C. mode 1: fused table-RoPE(+q scale) epilogue.
// ---------------------------------------------------------------------------
#define GPITCH 144               // 64 halfs = 128B data + 16B pad
#define PLANE  (128 * GPITCH)    // 18432 per plane
#define STAGE  (2 * PLANE)       // 36864 per stage (Ah, Bh)

__global__ void __launch_bounds__(256, 2)
gemm_fp16(const __half* __restrict__ Ah, const __half* __restrict__ Bh,
          float* __restrict__ C, int M, int N, int K, int mode)
{
    extern __shared__ char smc[];
    uint32_t sbase = smem_u32(smc);

    const int tid  = threadIdx.x;
    const int lane = tid & 31;
    const int wid  = tid >> 5;
    const int m0 = blockIdx.y * 128;
    const int n0 = blockIdx.x * 128;
    const int wm = (wid & 3) * 32;
    const int wn = (wid >> 2) * 64;

    const __half* gA0 = Ah + (size_t)m0 * K;
    const __half* gB0 = Bh + (size_t)n0 * K;

    auto load_stage = [&](int s, int k0) {
        uint32_t sp = sbase + s * STAGE;
        #pragma unroll
        for (int i = 0; i < 4; i++) {
            int idx = tid + i * 256;      // 0..1023
            int r = idx >> 3;             // 0..127
            int c = idx & 7;              // 16B chunk within 128B row
            uint32_t so = r * GPITCH + c * 16;
            size_t go = (size_t)r * K + k0 + c * 8;
            cpasync16(sp + so,         gA0 + go);
            cpasync16(sp + PLANE + so, gB0 + go);
        }
        asm volatile("cp.async.commit_group;");
    };

    float acc[2][8][4];
    #pragma unroll
    for (int a = 0; a < 2; a++)
        #pragma unroll
        for (int b = 0; b < 8; b++)
            #pragma unroll
            for (int c = 0; c < 4; c++) acc[a][b][c] = 0.f;

    const int nk = K >> 6;
    load_stage(0, 0);

    const int grp = lane >> 3, r8 = lane & 7;
    const int arow_off = r8 + ((grp & 1) << 3);
    const int akk_off  = (grp >> 1) << 3;
    const int brow_off = r8 + ((grp >> 1) << 3);
    const int bkk_off  = (grp & 1) << 3;

    for (int kt = 0; kt < nk; kt++) {
        int cur = kt & 1;
        if (kt + 1 < nk) {
            load_stage(cur ^ 1, (kt + 1) << 6);
            asm volatile("cp.async.wait_group 1;");
        } else {
            asm volatile("cp.async.wait_group 0;");
        }
        __syncthreads();

        uint32_t stg = sbase + cur * STAGE;
        uint32_t sAh = stg, sBh = stg + PLANE;

        #pragma unroll
        for (int ks = 0; ks < 4; ks++) {
            int kb = ks * 16;
            uint32_t a_h[2][4];
            #pragma unroll
            for (int mt = 0; mt < 2; mt++) {
                uint32_t ad = (uint32_t)((wm + mt * 16 + arow_off) * GPITCH
                                         + (kb + akk_off) * 2);
                ldsm4(a_h[mt], sAh + ad);
            }
            #pragma unroll
            for (int np = 0; np < 4; np++) {
                uint32_t bh[4];
                uint32_t bd = (uint32_t)((wn + np * 16 + brow_off) * GPITCH
                                         + (kb + bkk_off) * 2);
                ldsm4(bh, sBh + bd);
                #pragma unroll
                for (int mt = 0; mt < 2; mt++) {
                    mma16816(acc[mt][np * 2],     a_h[mt], &bh[0]);
                    mma16816(acc[mt][np * 2 + 1], a_h[mt], &bh[2]);
                }
            }
        }
        __syncthreads();
    }

    if (mode == 0) {
        #pragma unroll
        for (int mt = 0; mt < 2; mt++) {
            int row0 = m0 + wm + mt * 16 + (lane >> 2);
            #pragma unroll
            for (int nt = 0; nt < 8; nt++) {
                int col = n0 + wn + nt * 8 + (lane & 3) * 2;
                *(float2*)(C + (size_t)row0 * N + col) =
                    make_float2(acc[mt][nt][0], acc[mt][nt][1]);
                *(float2*)(C + (size_t)(row0 + 8) * N + col) =
                    make_float2(acc[mt][nt][2], acc[mt][nt][3]);
            }
        }
    } else {
        // QKV epilogue: fp32 tile via smem, table RoPE + scale, fp16 planes
        const int PITW = 134;   // 128*134*4 = 68608 <= 73728
        float* sf = (float*)smc;
        #pragma unroll
        for (int mt = 0; mt < 2; mt++) {
            int r0 = wm + mt * 16 + (lane >> 2);
            #pragma unroll
            for (int nt = 0; nt < 8; nt++) {
                int c = wn + nt * 8 + (lane & 3) * 2;
                sf[r0 * PITW + c]           = acc[mt][nt][0];
                sf[r0 * PITW + c + 1]       = acc[mt][nt][1];
                sf[(r0 + 8) * PITW + c]     = acc[mt][nt][2];
                sf[(r0 + 8) * PITW + c + 1] = acc[mt][nt][3];
            }
        }
        __syncthreads();

        int sec  = n0 >> 11;            // 0=q, 1=k, 2=v
        int head = (n0 >> 7) & 15;
        __half* dst = (sec == 0) ? g_qh : (sec == 1) ? g_kh : g_vh;
        size_t base_o = (size_t)head * SEQ * HD;
        float qscale = (sec == 0) ? 0.08838834764831845f : 1.0f;

        #pragma unroll 4
        for (int it = 0; it < 16; it++) {
            int idx = tid + it * 256;
            int r = idx >> 5;
            int i = (idx & 31) * 2;
            float x0 = sf[r * PITW + i],      x1 = sf[r * PITW + i + 1];
            float y0 = sf[r * PITW + i + 64], y1 = sf[r * PITW + i + 65];
            float re0, re1, im0, im1;
            if (sec < 2) {
                float4 t = *(float4*)&g_rope[(size_t)(m0 + r) * 64 + i];
                re0 = (x0 * t.x - y0 * t.y) * qscale;
                im0 = (y0 * t.x + x0 * t.y) * qscale;
                re1 = (x1 * t.z - y1 * t.w) * qscale;
                im1 = (y1 * t.z + x1 * t.w) * qscale;
            } else {
                re0 = x0; re1 = x1; im0 = y0; im1 = y1;
            }
            size_t o = base_o + (size_t)(m0 + r) * HD + i;
            *(uint32_t*)(dst + o)      = pack_hi(re0, re1);
            *(uint32_t*)(dst + o + 64) = pack_hi(im0, im1);
        }
    }
}

// ---------------------------------------------------------------------------
// fp16 HMMA flash attention (round-12 verified form).
// ---------------------------------------------------------------------------
#define FSW(row, c16) (((row) << 8) + ((((c16) ^ ((row) & 7))) << 4))
#define KVPL 16384
#define KVST 32768

__global__ void __launch_bounds__(256) flash_hmma()
{
    extern __shared__ char fsm[];
    uint32_t sQh = smem_u32(fsm);
    uint32_t sKV = sQh + 32768;

    const int tid  = threadIdx.x;
    const int lane = tid & 31;
    const int w    = tid >> 5;
    const int head = blockIdx.y;
    const int q0   = ((int)gridDim.x - 1 - (int)blockIdx.x) * 128;

    const size_t hoff = (size_t)head * SEQ * HD;
    const __half* Qh = g_qh + hoff;
    const __half* Kh = g_kh + hoff;
    const __half* Vh = g_vh + hoff;

    #pragma unroll
    for (int i = 0; i < 8; i++) {
        int idx = tid + i * 256;
        int r = idx >> 4, c16 = idx & 15;
        cpasync16(sQh + FSW(r, c16), Qh + (size_t)(q0 + r) * HD + c16 * 8);
    }

    auto load_kv = [&](int kt) {
        int k0 = kt << 6;
        uint32_t st = sKV + (kt & 1) * KVST;
        #pragma unroll
        for (int i = 0; i < 4; i++) {
            int idx = tid + i * 256;
            int r = idx >> 4, c16 = idx & 15;
            uint32_t o = FSW(r, c16);
            size_t go = (size_t)(k0 + r) * HD + c16 * 8;
            cpasync16(st + o,        Kh + go);
            cpasync16(st + KVPL + o, Vh + go);
        }
        asm volatile("cp.async.commit_group;");
    };

    const int ntk = (q0 >> 6) + 2;
    load_kv(0);

    const int grp = lane >> 3, r8 = lane & 7;
    const int arow = r8 + ((grp & 1) << 3);
    const int ac16 = grp >> 1;
    const int brow = r8 + ((grp >> 1) << 3);
    const int bc16 = grp & 1;

    float o[16][4];
    #pragma unroll
    for (int i = 0; i < 16; i++)
        #pragma unroll
        for (int j = 0; j < 4; j++) o[i][j] = 0.f;
    float m0 = -1e30f, m1 = -1e30f, l0 = 0.f, l1 = 0.f;

    const int row0 = q0 + w * 16 + (lane >> 2);
    const int wlast = q0 + w * 16 + 15;

    for (int kt = 0; kt < ntk; kt++) {
        int k0 = kt << 6;
        int cur = kt & 1;
        if (kt + 1 < ntk) {
            load_kv(kt + 1);
            asm volatile("cp.async.wait_group 1;");
        } else {
            asm volatile("cp.async.wait_group 0;");
        }
        __syncthreads();

        if (k0 <= wlast) {
            uint32_t st = sKV + cur * KVST;
            uint32_t sKh = st, sVh = st + KVPL;

            float sc[8][4];
            #pragma unroll
            for (int i = 0; i < 8; i++)
                #pragma unroll
                for (int j = 0; j < 4; j++) sc[i][j] = 0.f;

            #pragma unroll
            for (int ks = 0; ks < 8; ks++) {
                uint32_t qh[4];
                int qr = w * 16 + arow, qc = ks * 2 + ac16;
                ldsm4(qh, sQh + FSW(qr, qc));
                #pragma unroll
                for (int g = 0; g < 4; g++) {
                    uint32_t kh[4];
                    int kr = g * 16 + brow, kc = ks * 2 + bc16;
                    ldsm4(kh, sKh + FSW(kr, kc));
                    mma16816(sc[g * 2],     qh, &kh[0]);
                    mma16816(sc[g * 2 + 1], qh, &kh[2]);
                }
            }

            if (k0 + 63 > row0) {
                #pragma unroll
                for (int nt = 0; nt < 8; nt++) {
                    int colb = k0 + nt * 8 + (lane & 3) * 2;
                    if (colb > row0)     sc[nt][0] = -1e30f;
                    if (colb + 1 > row0) sc[nt][1] = -1e30f;
                    if (colb > row0 + 8)     sc[nt][2] = -1e30f;
                    if (colb + 1 > row0 + 8) sc[nt][3] = -1e30f;
                }
            }

            float mt0 = -1e30f, mt1 = -1e30f;
            #pragma unroll
            for (int nt = 0; nt < 8; nt++) {
                mt0 = fmaxf(mt0, fmaxf(sc[nt][0], sc[nt][1]));
                mt1 = fmaxf(mt1, fmaxf(sc[nt][2], sc[nt][3]));
            }
            mt0 = fmaxf(mt0, __shfl_xor_sync(0xffffffffu, mt0, 1));
            mt0 = fmaxf(mt0, __shfl_xor_sync(0xffffffffu, mt0, 2));
            mt1 = fmaxf(mt1, __shfl_xor_sync(0xffffffffu, mt1, 1));
            mt1 = fmaxf(mt1, __shfl_xor_sync(0xffffffffu, mt1, 2));
            float mn0 = fmaxf(m0, mt0), mn1 = fmaxf(m1, mt1);
            float f0 = __expf(m0 - mn0), f1 = __expf(m1 - mn1);
            m0 = mn0; m1 = mn1;

            float s0 = 0.f, s1 = 0.f;
            #pragma unroll
            for (int nt = 0; nt < 8; nt++) {
                sc[nt][0] = __expf(sc[nt][0] - mn0); s0 += sc[nt][0];
                sc[nt][1] = __expf(sc[nt][1] - mn0); s0 += sc[nt][1];
                sc[nt][2] = __expf(sc[nt][2] - mn1); s1 += sc[nt][2];
                sc[nt][3] = __expf(sc[nt][3] - mn1); s1 += sc[nt][3];
            }
            s0 += __shfl_xor_sync(0xffffffffu, s0, 1);
            s0 += __shfl_xor_sync(0xffffffffu, s0, 2);
            s1 += __shfl_xor_sync(0xffffffffu, s1, 1);
            s1 += __shfl_xor_sync(0xffffffffu, s1, 2);
            l0 = l0 * f0 + s0;
            l1 = l1 * f1 + s1;

            #pragma unroll
            for (int i = 0; i < 16; i++) {
                o[i][0] *= f0; o[i][1] *= f0;
                o[i][2] *= f1; o[i][3] *= f1;
            }

            #pragma unroll
            for (int ks = 0; ks < 4; ks++) {
                uint32_t ph[4];
                int t0 = ks * 2, t1 = ks * 2 + 1;
                ph[0] = pack_hi(sc[t0][0], sc[t0][1]);
                ph[1] = pack_hi(sc[t0][2], sc[t0][3]);
                ph[2] = pack_hi(sc[t1][0], sc[t1][1]);
                ph[3] = pack_hi(sc[t1][2], sc[t1][3]);
                #pragma unroll
                for (int g = 0; g < 8; g++) {
                    uint32_t vh[4];
                    int vr = ks * 16 + arow, vc = g * 2 + ac16;
                    ldsm4t(vh, sVh + FSW(vr, vc));
                    mma16816(o[g * 2],     ph, &vh[0]);
                    mma16816(o[g * 2 + 1], ph, &vh[2]);
                }
            }
        }
        __syncthreads();
    }

    float il0 = 1.0f / l0, il1 = 1.0f / l1;
    #pragma unroll
    for (int dt = 0; dt < 16; dt++) {
        int col = head * HD + dt * 8 + (lane & 3) * 2;
        *(uint32_t*)(g_at_h + (size_t)row0 * HID + col) =
            pack_hi(o[dt][0] * il0, o[dt][1] * il0);
        *(uint32_t*)(g_at_h + (size_t)(row0 + 8) * HID + col) =
            pack_hi(o[dt][2] * il1, o[dt][3] * il1);
    }
}

// ---------------------------------------------------------------------------
extern "C" void kernel_launch(void* const* d_in, const int* in_sizes, int n_in,
                              void* d_out, int out_size)
{
    const float* hidden = (const float*)d_in[0];
    const float* w_qkv  = (const float*)d_in[1];
    const float* w_o    = (const float*)d_in[2];
    float* out = (float*)d_out;

    __half *hid_h, *wq_h, *wo_h, *at_h;
    cudaGetSymbolAddress((void**)&hid_h, g_hid_h);
    cudaGetSymbolAddress((void**)&wq_h, g_wq_h);
    cudaGetSymbolAddress((void**)&wo_h, g_wo_h);
    cudaGetSymbolAddress((void**)&at_h, g_at_h);

    const int gemm_smem = 2 * STAGE;   // 73728
    cudaFuncSetAttribute(gemm_fp16,
                         cudaFuncAttributeMaxDynamicSharedMemorySize, gemm_smem);

    rope_table_kernel<<<SEQ * 64 / 256, 256>>>();
    cvt_kernel<<<(SEQ * HID / 4 + 255) / 256, 256>>>(hidden, hid_h, SEQ * HID / 4);
    cvt_kernel<<<(QKVN * HID / 4 + 255) / 256, 256>>>(w_qkv, wq_h, QKVN * HID / 4);
    cvt_kernel<<<(HID * HID / 4 + 255) / 256, 256>>>(w_o, wo_h, HID * HID / 4);

    // 1) QKV projection + fused RoPE/split epilogue
    gemm_fp16<<<dim3(QKVN / 128, SEQ / 128), 256, gemm_smem>>>(
        hid_h, wq_h, nullptr, SEQ, QKVN, HID, 1);

    // 2) flash attention
    const int fl_smem = 32768 + 2 * KVST;   // 98304
    cudaFuncSetAttribute(flash_hmma,
                         cudaFuncAttributeMaxDynamicSharedMemorySize, fl_smem);
    flash_hmma<<<dim3(SEQ / 128, NHEADS), 256, fl_smem>>>();

    // 3) O projection
    gemm_fp16<<<dim3(HID / 128, SEQ / 128), 256, gemm_smem>>>(
        at_h, wo_h, out, SEQ, HID, HID, 0);
}